// round 6
// baseline (speedup 1.0000x reference)
#include <cuda_runtime.h>
#include <cuda_bf16.h>

// ---------------- problem constants ----------------
constexpr int N_   = 40000;   // nodes
constexpr int E_   = 150000;  // edges per type
constexpr int H_   = 4;       // heads
constexpr int D_   = 128;     // per-head dim
constexpr int F_   = 512;     // H_*D_
constexpr int IN0_ = 1024;    // input feature dim
constexpr int OUT_ = 2983;    // output classes
constexpr size_t NF_ = (size_t)N_ * F_;
constexpr size_t NH_ = (size_t)N_ * H_;
constexpr size_t EH_ = (size_t)E_ * H_;

// ---------------- device scratch (no allocations allowed) ----------------
__device__ __align__(256) float    g_feat[2 * NF_];   // per-edge-type node features
__device__ __align__(256) float    g_h0[NF_];         // hidden ping
__device__ __align__(256) float    g_h1[NF_];         // hidden pong
__device__ __align__(256) float    g_acc[2 * NF_];    // PER-TYPE layer output accumulators
__device__ __align__(256) float    g_el[2 * NH_];
__device__ __align__(256) float    g_er[2 * NH_];
__device__ __align__(256) unsigned g_m[2 * NH_];      // segment max (order-encoded uint)
__device__ __align__(256) float    g_s[2 * NH_];      // segment expsum
__device__ __align__(256) float    g_w[2 * EH_];      // edge logits -> exp weights

// ---------------- helpers ----------------
__device__ __forceinline__ unsigned float_enc(float f) {
    unsigned u = __float_as_uint(f);
    return (u & 0x80000000u) ? ~u : (u | 0x80000000u);
}
__device__ __forceinline__ float float_dec(unsigned e) {
    unsigned u = (e & 0x80000000u) ? (e & 0x7FFFFFFFu) : ~e;
    return __uint_as_float(u);
}
__device__ __forceinline__ float lrelu(float v, float s) {
    return (v > 0.f) ? v : s * v;
}

// ---------------- zero kernel (float4) ----------------
__global__ void zero4_kernel(float4* __restrict__ p, size_t n4) {
    size_t i = (size_t)blockIdx.x * blockDim.x + threadIdx.x;
    if (i < n4) p[i] = make_float4(0.f, 0.f, 0.f, 0.f);
}

// ---------------- fp32 SGEMM: C[M,Nn] = A[M,K] @ B[K,Nn] (+bias) ----------------
// 128x128 block, 8x8 per thread, BK=8, 256 threads.
constexpr int BM = 128, BN = 128, BK = 8, TM = 8, TN = 8;

__global__ void __launch_bounds__(256)
sgemm_kernel(const float* __restrict__ A, const float* __restrict__ B,
             float* __restrict__ C, int M, int Nn, int K,
             const float* __restrict__ bias) {
    __shared__ float As[BK][BM];
    __shared__ float Bs[BK][BN];

    const int tid  = threadIdx.x;
    const int trow = tid >> 4;   // 0..15
    const int tcol = tid & 15;   // 0..15
    const int rowBase = blockIdx.y * BM;
    const int colBase = blockIdx.x * BN;

    float acc[TM][TN];
#pragma unroll
    for (int i = 0; i < TM; i++)
#pragma unroll
        for (int j = 0; j < TN; j++) acc[i][j] = 0.f;

    const int aRow = tid >> 1;          // 0..127
    const int aCol = (tid & 1) * 4;     // 0 or 4

    for (int k0 = 0; k0 < K; k0 += BK) {
        // load A tile (vectorized; K is a multiple of 8 in all our calls)
        {
            int gr = rowBase + aRow;
            float4 av = make_float4(0.f, 0.f, 0.f, 0.f);
            if (gr < M) av = *reinterpret_cast<const float4*>(A + (size_t)gr * K + k0 + aCol);
            As[aCol + 0][aRow] = av.x;
            As[aCol + 1][aRow] = av.y;
            As[aCol + 2][aRow] = av.z;
            As[aCol + 3][aRow] = av.w;
        }
        // load B tile (scalar: Nn=2983 rows are not 16B aligned)
#pragma unroll
        for (int i = 0; i < 4; i++) {
            int e  = tid + i * 256;
            int br = e >> 7;       // 0..7
            int bc = e & 127;
            int gc = colBase + bc;
            Bs[br][bc] = (gc < Nn) ? B[(size_t)(k0 + br) * Nn + gc] : 0.f;
        }
        __syncthreads();

#pragma unroll
        for (int k = 0; k < BK; k++) {
            float a[TM], b[TN];
            const float4* ap = reinterpret_cast<const float4*>(&As[k][trow * TM]);
            float4 a0 = ap[0], a1 = ap[1];
            a[0]=a0.x; a[1]=a0.y; a[2]=a0.z; a[3]=a0.w;
            a[4]=a1.x; a[5]=a1.y; a[6]=a1.z; a[7]=a1.w;
            const float4* bp = reinterpret_cast<const float4*>(&Bs[k][tcol * TN]);
            float4 b0 = bp[0], b1 = bp[1];
            b[0]=b0.x; b[1]=b0.y; b[2]=b0.z; b[3]=b0.w;
            b[4]=b1.x; b[5]=b1.y; b[6]=b1.z; b[7]=b1.w;
#pragma unroll
            for (int i = 0; i < TM; i++)
#pragma unroll
                for (int j = 0; j < TN; j++)
                    acc[i][j] = fmaf(a[i], b[j], acc[i][j]);
        }
        __syncthreads();
    }

#pragma unroll
    for (int i = 0; i < TM; i++) {
        int r = rowBase + trow * TM + i;
        if (r >= M) continue;
#pragma unroll
        for (int j = 0; j < TN; j++) {
            int c = colBase + tcol * TN + j;
            if (c < Nn) {
                float v = acc[i][j];
                if (bias) v += bias[c];
                C[(size_t)r * Nn + c] = v;
            }
        }
    }
}

// ---------------- attention projections: el/er [N,H] ----------------
// one warp per (node, head)
__global__ void attn_kernel(const float* __restrict__ feat,
                            const float* __restrict__ al,
                            const float* __restrict__ ar,
                            float* __restrict__ el, float* __restrict__ er) {
    int gw   = (blockIdx.x * blockDim.x + threadIdx.x) >> 5;
    int lane = threadIdx.x & 31;
    if (gw >= N_ * H_) return;
    int h = gw & (H_ - 1);

    float4 f = reinterpret_cast<const float4*>(feat + (size_t)gw * D_)[lane];
    float4 a = reinterpret_cast<const float4*>(al + h * D_)[lane];
    float4 r = reinterpret_cast<const float4*>(ar + h * D_)[lane];
    float sl = f.x*a.x + f.y*a.y + f.z*a.z + f.w*a.w;
    float sr = f.x*r.x + f.y*r.y + f.z*r.z + f.w*r.w;
#pragma unroll
    for (int o = 16; o > 0; o >>= 1) {
        sl += __shfl_down_sync(0xFFFFFFFFu, sl, o);
        sr += __shfl_down_sync(0xFFFFFFFFu, sr, o);
    }
    if (lane == 0) { el[gw] = sl; er[gw] = sr; }
}

// ---------------- edge pass 1: logits + segment max ----------------
__global__ void edge_logits_kernel(const int* __restrict__ src, const int* __restrict__ dst,
                                   const float* __restrict__ el, const float* __restrict__ er,
                                   float* __restrict__ ew, unsigned* __restrict__ m) {
    int i = blockIdx.x * blockDim.x + threadIdx.x;
    if (i >= E_ * H_) return;
    int e = i >> 2, h = i & 3;
    int s = src[e], d = dst[e];
    float v = el[s * H_ + h] + er[d * H_ + h];
    v = lrelu(v, 0.2f);
    ew[i] = v;
    atomicMax(&m[d * H_ + h], float_enc(v));
}

// ---------------- edge pass 2: exp + segment sum ----------------
__global__ void edge_exp_kernel(const int* __restrict__ dst,
                                float* __restrict__ ew, const unsigned* __restrict__ m,
                                float* __restrict__ ssum) {
    int i = blockIdx.x * blockDim.x + threadIdx.x;
    if (i >= E_ * H_) return;
    int e = i >> 2, h = i & 3;
    int d = dst[e];
    float w = expf(ew[i] - float_dec(m[d * H_ + h]));
    ew[i] = w;
    atomicAdd(&ssum[d * H_ + h], w);
}

// ---------------- edge pass 3: weighted scatter-add of messages ----------------
// one warp per (edge, head); each lane handles 4 consecutive dims
__global__ void edge_scatter_kernel(const int* __restrict__ src, const int* __restrict__ dst,
                                    const float* __restrict__ ew, const float* __restrict__ ssum,
                                    const float* __restrict__ feat, float* __restrict__ acc) {
    int gw   = (blockIdx.x * blockDim.x + threadIdx.x) >> 5;
    int lane = threadIdx.x & 31;
    if (gw >= E_ * H_) return;
    int e = gw >> 2, h = gw & 3;
    int s = src[e], d = dst[e];
    float a = ew[gw] / ssum[d * H_ + h];

    float4 v = reinterpret_cast<const float4*>(feat + ((size_t)s * H_ + h) * D_)[lane];
    float* o = acc + ((size_t)d * H_ + h) * D_ + lane * 4;
    atomicAdd(o + 0, v.x * a);
    atomicAdd(o + 1, v.y * a);
    atomicAdd(o + 2, v.z * a);
    atomicAdd(o + 3, v.w * a);
}

// ---------------- finalize ----------------
// PER-TYPE: hout = act(acc0 + b0) + act(acc1 + b1)   (activation per edge type!)
__global__ void finalize_kernel(const float4* __restrict__ acc0, const float4* __restrict__ acc1,
                                const float4* __restrict__ b0, const float4* __restrict__ b1,
                                float4* __restrict__ hout, int activate) {
    size_t i = (size_t)blockIdx.x * blockDim.x + threadIdx.x;
    if (i >= NF_ / 4) return;
    int c4 = (int)(i & (F_ / 4 - 1));   // F_/4 = 128 column-vectors per row
    float4 v0 = acc0[i];
    float4 v1 = acc1[i];
    float4 x0 = b0[c4];
    float4 x1 = b1[c4];
    v0.x += x0.x; v0.y += x0.y; v0.z += x0.z; v0.w += x0.w;
    v1.x += x1.x; v1.y += x1.y; v1.z += x1.z; v1.w += x1.w;
    if (activate) {
        v0.x = lrelu(v0.x, 0.01f); v0.y = lrelu(v0.y, 0.01f);
        v0.z = lrelu(v0.z, 0.01f); v0.w = lrelu(v0.w, 0.01f);
        v1.x = lrelu(v1.x, 0.01f); v1.y = lrelu(v1.y, 0.01f);
        v1.z = lrelu(v1.z, 0.01f); v1.w = lrelu(v1.w, 0.01f);
    }
    float4 v;
    v.x = v0.x + v1.x; v.y = v0.y + v1.y; v.z = v0.z + v1.z; v.w = v0.w + v1.w;
    hout[i] = v;
}

// ---------------- host orchestration ----------------
extern "C" void kernel_launch(void* const* d_in, const int* in_sizes, int n_in,
                              void* d_out, int out_size) {
    const float* x       = (const float*)d_in[0];
    const int*   srcs[2] = {(const int*)d_in[1], (const int*)d_in[3]};
    const int*   dsts[2] = {(const int*)d_in[2], (const int*)d_in[4]};
    const float* W[3]    = {(const float*)d_in[5],  (const float*)d_in[9],  (const float*)d_in[13]};
    const float* AL[3]   = {(const float*)d_in[6],  (const float*)d_in[10], (const float*)d_in[14]};
    const float* AR[3]   = {(const float*)d_in[7],  (const float*)d_in[11], (const float*)d_in[15]};
    const float* BB[3]   = {(const float*)d_in[8],  (const float*)d_in[12], (const float*)d_in[16]};
    const float* Wout    = (const float*)d_in[17];
    const float* bout    = (const float*)d_in[18];
    float*       out     = (float*)d_out;

    void* p;
    cudaGetSymbolAddress(&p, g_feat); float*    feat = (float*)p;
    cudaGetSymbolAddress(&p, g_h0);   float*    h0   = (float*)p;
    cudaGetSymbolAddress(&p, g_h1);   float*    h1   = (float*)p;
    cudaGetSymbolAddress(&p, g_acc);  float*    acc  = (float*)p;
    cudaGetSymbolAddress(&p, g_el);   float*    el   = (float*)p;
    cudaGetSymbolAddress(&p, g_er);   float*    er   = (float*)p;
    cudaGetSymbolAddress(&p, g_m);    unsigned* mx   = (unsigned*)p;
    cudaGetSymbolAddress(&p, g_s);    float*    ss   = (float*)p;
    cudaGetSymbolAddress(&p, g_w);    float*    ew   = (float*)p;
    float* hb[2] = {h0, h1};

    const float* hin = x;
    int K = IN0_;

    for (int L = 0; L < 3; L++) {
        // reset per-type accumulators / segment stats
        {
            size_t n4 = (2 * NF_) / 4;
            zero4_kernel<<<(unsigned)((n4 + 255) / 256), 256>>>((float4*)acc, n4);
            size_t m4 = (2 * NH_) / 4;
            zero4_kernel<<<(unsigned)((m4 + 255) / 256), 256>>>((float4*)mx, m4);
            zero4_kernel<<<(unsigned)((m4 + 255) / 256), 256>>>((float4*)ss, m4);
        }
        for (int t = 0; t < 2; t++) {
            float*    featT = feat + (size_t)t * NF_;
            float*    accT  = acc  + (size_t)t * NF_;
            float*    elT   = el + (size_t)t * NH_;
            float*    erT   = er + (size_t)t * NH_;
            unsigned* mT    = mx + (size_t)t * NH_;
            float*    sT    = ss + (size_t)t * NH_;
            float*    wT    = ew + (size_t)t * EH_;

            dim3 grid((F_ + BN - 1) / BN, (N_ + BM - 1) / BM);
            sgemm_kernel<<<grid, 256>>>(hin, W[L] + (size_t)t * K * F_, featT,
                                        N_, F_, K, nullptr);

            attn_kernel<<<(N_ * H_ * 32 + 255) / 256, 256>>>(
                featT, AL[L] + t * H_ * D_, AR[L] + t * H_ * D_, elT, erT);

            edge_logits_kernel<<<(E_ * H_ + 255) / 256, 256>>>(
                srcs[t], dsts[t], elT, erT, wT, mT);

            edge_exp_kernel<<<(E_ * H_ + 255) / 256, 256>>>(dsts[t], wT, mT, sT);

            edge_scatter_kernel<<<(E_ * H_ + 7) / 8, 256>>>(
                srcs[t], dsts[t], wT, sT, featT, accT);
        }
        finalize_kernel<<<(unsigned)((NF_ / 4 + 255) / 256), 256>>>(
            (const float4*)acc, (const float4*)(acc + NF_),
            (const float4*)BB[L], (const float4*)(BB[L] + F_),
            (float4*)hb[L & 1], (L < 2) ? 1 : 0);
        hin = hb[L & 1];
        K = F_;
    }

    // output projection: [N, 512] @ [512, 2983] + bout
    dim3 grid((OUT_ + BN - 1) / BN, (N_ + BM - 1) / BM);
    sgemm_kernel<<<grid, 256>>>(hin, Wout, out, N_, OUT_, F_, bout);
}

// round 7
// speedup vs baseline: 2.6750x; 2.6750x over previous
#include <cuda_runtime.h>
#include <cuda_bf16.h>

// ---------------- problem constants ----------------
constexpr int N_   = 40000;   // nodes
constexpr int E_   = 150000;  // edges per type
constexpr int H_   = 4;       // heads
constexpr int D_   = 128;     // per-head dim
constexpr int F_   = 512;     // H_*D_
constexpr int IN0_ = 1024;    // input feature dim
constexpr int OUT_ = 2983;    // output classes
constexpr size_t NF_ = (size_t)N_ * F_;
constexpr size_t NH_ = (size_t)N_ * H_;
constexpr size_t EH_ = (size_t)E_ * H_;

// ---------------- device scratch (no allocations allowed) ----------------
__device__ __align__(256) float    g_feat[2 * NF_];   // per-edge-type node features
__device__ __align__(256) float    g_h0[NF_];         // hidden ping
__device__ __align__(256) float    g_h1[NF_];         // hidden pong
__device__ __align__(256) float    g_acc[2 * NF_];    // PER-TYPE layer output accumulators
__device__ __align__(256) float    g_el[2 * NH_];
__device__ __align__(256) float    g_er[2 * NH_];
__device__ __align__(256) unsigned g_m[2 * NH_];      // segment max (order-encoded uint)
__device__ __align__(256) float    g_s[2 * NH_];      // segment expsum
__device__ __align__(256) float    g_w[2 * EH_];      // edge logits -> exp weights

// ---------------- helpers ----------------
__device__ __forceinline__ unsigned float_enc(float f) {
    unsigned u = __float_as_uint(f);
    return (u & 0x80000000u) ? ~u : (u | 0x80000000u);
}
__device__ __forceinline__ float float_dec(unsigned e) {
    unsigned u = (e & 0x80000000u) ? (e & 0x7FFFFFFFu) : ~e;
    return __uint_as_float(u);
}
__device__ __forceinline__ float lrelu(float v, float s) {
    return (v > 0.f) ? v : s * v;
}
__device__ __forceinline__ unsigned f2tf32(float x) {
    unsigned r;
    asm("cvt.rna.tf32.f32 %0, %1;" : "=r"(r) : "f"(x));
    return r;
}
__device__ __forceinline__ void mma_tf32(float c[4],
                                         unsigned a0, unsigned a1, unsigned a2, unsigned a3,
                                         unsigned b0, unsigned b1) {
    asm volatile(
        "mma.sync.aligned.m16n8k8.row.col.f32.tf32.tf32.f32 "
        "{%0,%1,%2,%3}, {%4,%5,%6,%7}, {%8,%9}, {%0,%1,%2,%3};"
        : "+f"(c[0]), "+f"(c[1]), "+f"(c[2]), "+f"(c[3])
        : "r"(a0), "r"(a1), "r"(a2), "r"(a3), "r"(b0), "r"(b1));
}

// ---------------- zero kernel (float4) ----------------
__global__ void zero4_kernel(float4* __restrict__ p, size_t n4) {
    size_t i = (size_t)blockIdx.x * blockDim.x + threadIdx.x;
    if (i < n4) p[i] = make_float4(0.f, 0.f, 0.f, 0.f);
}

// ---------------- TF32 tensor-core GEMM: C[M,Nn] = A[M,K] @ B[K,Nn] (+bias) ----
// 128x128 block tile, BK=16, 256 threads = 8 warps (2x4), warp tile 64x32.
// mma.sync m16n8k8 tf32, fp32 accumulate. Register-staged double buffer in smem.
constexpr int TBM = 128, TBN = 128, TBK = 16;
constexpr int SPITCH = 132;   // padded row pitch (words) -> conflict-free frag loads

__global__ void __launch_bounds__(256, 2)
tgemm_kernel(const float* __restrict__ A, const float* __restrict__ B,
             float* __restrict__ C, int M, int Nn, int K,
             const float* __restrict__ bias) {
    __shared__ unsigned As[2][TBK][SPITCH];
    __shared__ unsigned Bs[2][TBK][SPITCH];

    const int tid  = threadIdx.x;
    const int lane = tid & 31;
    const int warp = tid >> 5;
    const int wr   = warp >> 2;      // 0..1
    const int wc   = warp & 3;       // 0..3
    const int gID  = lane >> 2;      // 0..7
    const int tig  = lane & 3;       // 0..3
    const int mBase = wr * 64;
    const int nBase = wc * 32;
    const int rowBase = blockIdx.y * TBM;
    const int colBase = blockIdx.x * TBN;

    // A staging: each thread loads 8 floats (2 float4) of one row
    const int ar = tid & 127;          // tile row
    const int ak = (tid >> 7) * 8;     // k offset: 0 or 8
    // B staging: each thread loads 8 floats, stride-16 within one k-row
    const int bk = tid >> 4;           // 0..15
    const int bc = tid & 15;           // col lane (stride 16)

    float acc[4][4][4];
#pragma unroll
    for (int mi = 0; mi < 4; mi++)
#pragma unroll
        for (int ni = 0; ni < 4; ni++)
#pragma unroll
            for (int q = 0; q < 4; q++) acc[mi][ni][q] = 0.f;

    float aReg[8], bReg[8];

    // ---- prologue: load tile 0 ----
    {
        const int gr = rowBase + ar;
        if (gr < M) {
            const float4 v0 = *reinterpret_cast<const float4*>(A + (size_t)gr * K + ak);
            const float4 v1 = *reinterpret_cast<const float4*>(A + (size_t)gr * K + ak + 4);
            aReg[0]=v0.x; aReg[1]=v0.y; aReg[2]=v0.z; aReg[3]=v0.w;
            aReg[4]=v1.x; aReg[5]=v1.y; aReg[6]=v1.z; aReg[7]=v1.w;
        } else {
#pragma unroll
            for (int j = 0; j < 8; j++) aReg[j] = 0.f;
        }
        const float* Bp = B + (size_t)bk * Nn;
#pragma unroll
        for (int j = 0; j < 8; j++) {
            int gc = colBase + bc + 16 * j;
            bReg[j] = (gc < Nn) ? Bp[gc] : 0.f;
        }
#pragma unroll
        for (int j = 0; j < 8; j++) As[0][ak + j][ar] = f2tf32(aReg[j]);
#pragma unroll
        for (int j = 0; j < 8; j++) Bs[0][bk][bc + 16 * j] = f2tf32(bReg[j]);
    }

    const int ntiles = K / TBK;
    for (int t = 0; t < ntiles; t++) {
        __syncthreads();
        const int buf = t & 1;

        // prefetch next tile into registers
        if (t + 1 < ntiles) {
            const int k0 = (t + 1) * TBK;
            const int gr = rowBase + ar;
            if (gr < M) {
                const float4 v0 = *reinterpret_cast<const float4*>(A + (size_t)gr * K + k0 + ak);
                const float4 v1 = *reinterpret_cast<const float4*>(A + (size_t)gr * K + k0 + ak + 4);
                aReg[0]=v0.x; aReg[1]=v0.y; aReg[2]=v0.z; aReg[3]=v0.w;
                aReg[4]=v1.x; aReg[5]=v1.y; aReg[6]=v1.z; aReg[7]=v1.w;
            } else {
#pragma unroll
                for (int j = 0; j < 8; j++) aReg[j] = 0.f;
            }
            const float* Bp = B + (size_t)(k0 + bk) * Nn;
#pragma unroll
            for (int j = 0; j < 8; j++) {
                int gc = colBase + bc + 16 * j;
                bReg[j] = (gc < Nn) ? Bp[gc] : 0.f;
            }
        }

        // mma over current buffer: two k=8 steps
#pragma unroll
        for (int ks = 0; ks < 2; ks++) {
            const int kk = ks * 8;
            unsigned af[4][4], bf[4][2];
#pragma unroll
            for (int mi = 0; mi < 4; mi++) {
                const int m0 = mBase + mi * 16 + gID;
                af[mi][0] = As[buf][kk + tig    ][m0];
                af[mi][1] = As[buf][kk + tig    ][m0 + 8];
                af[mi][2] = As[buf][kk + tig + 4][m0];
                af[mi][3] = As[buf][kk + tig + 4][m0 + 8];
            }
#pragma unroll
            for (int ni = 0; ni < 4; ni++) {
                const int n0 = nBase + ni * 8 + gID;
                bf[ni][0] = Bs[buf][kk + tig    ][n0];
                bf[ni][1] = Bs[buf][kk + tig + 4][n0];
            }
#pragma unroll
            for (int mi = 0; mi < 4; mi++)
#pragma unroll
                for (int ni = 0; ni < 4; ni++)
                    mma_tf32(acc[mi][ni], af[mi][0], af[mi][1], af[mi][2], af[mi][3],
                             bf[ni][0], bf[ni][1]);
        }

        // stage next tile into the other buffer
        if (t + 1 < ntiles) {
            const int nb = buf ^ 1;
#pragma unroll
            for (int j = 0; j < 8; j++) As[nb][ak + j][ar] = f2tf32(aReg[j]);
#pragma unroll
            for (int j = 0; j < 8; j++) Bs[nb][bk][bc + 16 * j] = f2tf32(bReg[j]);
        }
    }

    // ---- epilogue ----
#pragma unroll
    for (int mi = 0; mi < 4; mi++) {
        const int r0 = rowBase + mBase + mi * 16 + gID;
        const int r1 = r0 + 8;
#pragma unroll
        for (int ni = 0; ni < 4; ni++) {
            const int c0 = colBase + nBase + ni * 8 + tig * 2;
            const int c1 = c0 + 1;
            float b0v = 0.f, b1v = 0.f;
            if (bias) {
                if (c0 < Nn) b0v = bias[c0];
                if (c1 < Nn) b1v = bias[c1];
            }
            if (r0 < M) {
                if (c0 < Nn) C[(size_t)r0 * Nn + c0] = acc[mi][ni][0] + b0v;
                if (c1 < Nn) C[(size_t)r0 * Nn + c1] = acc[mi][ni][1] + b1v;
            }
            if (r1 < M) {
                if (c0 < Nn) C[(size_t)r1 * Nn + c0] = acc[mi][ni][2] + b0v;
                if (c1 < Nn) C[(size_t)r1 * Nn + c1] = acc[mi][ni][3] + b1v;
            }
        }
    }
}

// ---------------- attention projections: el/er [N,H] ----------------
// one warp per (node, head)
__global__ void attn_kernel(const float* __restrict__ feat,
                            const float* __restrict__ al,
                            const float* __restrict__ ar,
                            float* __restrict__ el, float* __restrict__ er) {
    int gw   = (blockIdx.x * blockDim.x + threadIdx.x) >> 5;
    int lane = threadIdx.x & 31;
    if (gw >= N_ * H_) return;
    int h = gw & (H_ - 1);

    float4 f = reinterpret_cast<const float4*>(feat + (size_t)gw * D_)[lane];
    float4 a = reinterpret_cast<const float4*>(al + h * D_)[lane];
    float4 r = reinterpret_cast<const float4*>(ar + h * D_)[lane];
    float sl = f.x*a.x + f.y*a.y + f.z*a.z + f.w*a.w;
    float sr = f.x*r.x + f.y*r.y + f.z*r.z + f.w*r.w;
#pragma unroll
    for (int o = 16; o > 0; o >>= 1) {
        sl += __shfl_down_sync(0xFFFFFFFFu, sl, o);
        sr += __shfl_down_sync(0xFFFFFFFFu, sr, o);
    }
    if (lane == 0) { el[gw] = sl; er[gw] = sr; }
}

// ---------------- edge pass 1: logits + segment max ----------------
__global__ void edge_logits_kernel(const int* __restrict__ src, const int* __restrict__ dst,
                                   const float* __restrict__ el, const float* __restrict__ er,
                                   float* __restrict__ ew, unsigned* __restrict__ m) {
    int i = blockIdx.x * blockDim.x + threadIdx.x;
    if (i >= E_ * H_) return;
    int e = i >> 2, h = i & 3;
    int s = src[e], d = dst[e];
    float v = el[s * H_ + h] + er[d * H_ + h];
    v = lrelu(v, 0.2f);
    ew[i] = v;
    atomicMax(&m[d * H_ + h], float_enc(v));
}

// ---------------- edge pass 2: exp + segment sum ----------------
__global__ void edge_exp_kernel(const int* __restrict__ dst,
                                float* __restrict__ ew, const unsigned* __restrict__ m,
                                float* __restrict__ ssum) {
    int i = blockIdx.x * blockDim.x + threadIdx.x;
    if (i >= E_ * H_) return;
    int e = i >> 2, h = i & 3;
    int d = dst[e];
    float w = expf(ew[i] - float_dec(m[d * H_ + h]));
    ew[i] = w;
    atomicAdd(&ssum[d * H_ + h], w);
}

// ---------------- edge pass 3: weighted scatter-add of messages ----------------
// one warp per (edge, head); each lane handles 4 consecutive dims
__global__ void edge_scatter_kernel(const int* __restrict__ src, const int* __restrict__ dst,
                                    const float* __restrict__ ew, const float* __restrict__ ssum,
                                    const float* __restrict__ feat, float* __restrict__ acc) {
    int gw   = (blockIdx.x * blockDim.x + threadIdx.x) >> 5;
    int lane = threadIdx.x & 31;
    if (gw >= E_ * H_) return;
    int e = gw >> 2, h = gw & 3;
    int s = src[e], d = dst[e];
    float a = ew[gw] / ssum[d * H_ + h];

    float4 v = reinterpret_cast<const float4*>(feat + ((size_t)s * H_ + h) * D_)[lane];
    float* o = acc + ((size_t)d * H_ + h) * D_ + lane * 4;
    atomicAdd(o + 0, v.x * a);
    atomicAdd(o + 1, v.y * a);
    atomicAdd(o + 2, v.z * a);
    atomicAdd(o + 3, v.w * a);
}

// ---------------- finalize ----------------
// PER-TYPE: hout = act(acc0 + b0) + act(acc1 + b1)   (activation per edge type!)
__global__ void finalize_kernel(const float4* __restrict__ acc0, const float4* __restrict__ acc1,
                                const float4* __restrict__ b0, const float4* __restrict__ b1,
                                float4* __restrict__ hout, int activate) {
    size_t i = (size_t)blockIdx.x * blockDim.x + threadIdx.x;
    if (i >= NF_ / 4) return;
    int c4 = (int)(i & (F_ / 4 - 1));   // F_/4 = 128 column-vectors per row
    float4 v0 = acc0[i];
    float4 v1 = acc1[i];
    float4 x0 = b0[c4];
    float4 x1 = b1[c4];
    v0.x += x0.x; v0.y += x0.y; v0.z += x0.z; v0.w += x0.w;
    v1.x += x1.x; v1.y += x1.y; v1.z += x1.z; v1.w += x1.w;
    if (activate) {
        v0.x = lrelu(v0.x, 0.01f); v0.y = lrelu(v0.y, 0.01f);
        v0.z = lrelu(v0.z, 0.01f); v0.w = lrelu(v0.w, 0.01f);
        v1.x = lrelu(v1.x, 0.01f); v1.y = lrelu(v1.y, 0.01f);
        v1.z = lrelu(v1.z, 0.01f); v1.w = lrelu(v1.w, 0.01f);
    }
    float4 v;
    v.x = v0.x + v1.x; v.y = v0.y + v1.y; v.z = v0.z + v1.z; v.w = v0.w + v1.w;
    hout[i] = v;
}

// ---------------- host orchestration ----------------
extern "C" void kernel_launch(void* const* d_in, const int* in_sizes, int n_in,
                              void* d_out, int out_size) {
    const float* x       = (const float*)d_in[0];
    const int*   srcs[2] = {(const int*)d_in[1], (const int*)d_in[3]};
    const int*   dsts[2] = {(const int*)d_in[2], (const int*)d_in[4]};
    const float* W[3]    = {(const float*)d_in[5],  (const float*)d_in[9],  (const float*)d_in[13]};
    const float* AL[3]   = {(const float*)d_in[6],  (const float*)d_in[10], (const float*)d_in[14]};
    const float* AR[3]   = {(const float*)d_in[7],  (const float*)d_in[11], (const float*)d_in[15]};
    const float* BB[3]   = {(const float*)d_in[8],  (const float*)d_in[12], (const float*)d_in[16]};
    const float* Wout    = (const float*)d_in[17];
    const float* bout    = (const float*)d_in[18];
    float*       out     = (float*)d_out;

    void* p;
    cudaGetSymbolAddress(&p, g_feat); float*    feat = (float*)p;
    cudaGetSymbolAddress(&p, g_h0);   float*    h0   = (float*)p;
    cudaGetSymbolAddress(&p, g_h1);   float*    h1   = (float*)p;
    cudaGetSymbolAddress(&p, g_acc);  float*    acc  = (float*)p;
    cudaGetSymbolAddress(&p, g_el);   float*    el   = (float*)p;
    cudaGetSymbolAddress(&p, g_er);   float*    er   = (float*)p;
    cudaGetSymbolAddress(&p, g_m);    unsigned* mx   = (unsigned*)p;
    cudaGetSymbolAddress(&p, g_s);    float*    ss   = (float*)p;
    cudaGetSymbolAddress(&p, g_w);    float*    ew   = (float*)p;
    float* hb[2] = {h0, h1};

    const float* hin = x;
    int K = IN0_;

    for (int L = 0; L < 3; L++) {
        // reset per-type accumulators / segment stats
        {
            size_t n4 = (2 * NF_) / 4;
            zero4_kernel<<<(unsigned)((n4 + 255) / 256), 256>>>((float4*)acc, n4);
            size_t m4 = (2 * NH_) / 4;
            zero4_kernel<<<(unsigned)((m4 + 255) / 256), 256>>>((float4*)mx, m4);
            zero4_kernel<<<(unsigned)((m4 + 255) / 256), 256>>>((float4*)ss, m4);
        }
        for (int t = 0; t < 2; t++) {
            float*    featT = feat + (size_t)t * NF_;
            float*    accT  = acc  + (size_t)t * NF_;
            float*    elT   = el + (size_t)t * NH_;
            float*    erT   = er + (size_t)t * NH_;
            unsigned* mT    = mx + (size_t)t * NH_;
            float*    sT    = ss + (size_t)t * NH_;
            float*    wT    = ew + (size_t)t * EH_;

            dim3 grid((F_ + TBN - 1) / TBN, (N_ + TBM - 1) / TBM);
            tgemm_kernel<<<grid, 256>>>(hin, W[L] + (size_t)t * K * F_, featT,
                                        N_, F_, K, nullptr);

            attn_kernel<<<(N_ * H_ * 32 + 255) / 256, 256>>>(
                featT, AL[L] + t * H_ * D_, AR[L] + t * H_ * D_, elT, erT);

            edge_logits_kernel<<<(E_ * H_ + 255) / 256, 256>>>(
                srcs[t], dsts[t], elT, erT, wT, mT);

            edge_exp_kernel<<<(E_ * H_ + 255) / 256, 256>>>(dsts[t], wT, mT, sT);

            edge_scatter_kernel<<<(E_ * H_ + 7) / 8, 256>>>(
                srcs[t], dsts[t], wT, sT, featT, accT);
        }
        finalize_kernel<<<(unsigned)((NF_ / 4 + 255) / 256), 256>>>(
            (const float4*)acc, (const float4*)(acc + NF_),
            (const float4*)BB[L], (const float4*)(BB[L] + F_),
            (float4*)hb[L & 1], (L < 2) ? 1 : 0);
        hin = hb[L & 1];
        K = F_;
    }

    // output projection: [N, 512] @ [512, 2983] + bout
    dim3 grid((OUT_ + TBN - 1) / TBN, (N_ + TBM - 1) / TBM);
    tgemm_kernel<<<grid, 256>>>(hin, Wout, out, N_, OUT_, F_, bout);
}

// round 11
// speedup vs baseline: 3.3594x; 1.2558x over previous
#include <cuda_runtime.h>
#include <cuda_bf16.h>

// ---------------- problem constants ----------------
constexpr int N_   = 40000;   // nodes
constexpr int E_   = 150000;  // edges per type
constexpr int H_   = 4;       // heads
constexpr int D_   = 128;     // per-head dim
constexpr int F_   = 512;     // H_*D_
constexpr int IN0_ = 1024;    // input feature dim
constexpr int OUT_ = 2983;    // output classes
constexpr size_t NF_ = (size_t)N_ * F_;
constexpr size_t NH_ = (size_t)N_ * H_;
constexpr size_t EH_ = (size_t)E_ * H_;

// ---------------- device scratch (no allocations allowed) ----------------
__device__ __align__(256) float    g_feat[2 * NF_];   // per-edge-type node features
__device__ __align__(256) float    g_h0[NF_];         // hidden ping
__device__ __align__(256) float    g_h1[NF_];         // hidden pong
__device__ __align__(256) float    g_acc[2 * NF_];    // PER-TYPE layer output accumulators
__device__ __align__(256) float    g_el[2 * NH_];
__device__ __align__(256) float    g_er[2 * NH_];
__device__ __align__(256) unsigned g_m[2 * NH_];      // segment max (order-encoded uint)
__device__ __align__(256) float    g_s[2 * NH_];      // segment expsum
__device__ __align__(256) float    g_w[2 * EH_];      // edge logits -> exp weights

// ---------------- helpers ----------------
__device__ __forceinline__ unsigned float_enc(float f) {
    unsigned u = __float_as_uint(f);
    return (u & 0x80000000u) ? ~u : (u | 0x80000000u);
}
__device__ __forceinline__ float float_dec(unsigned e) {
    unsigned u = (e & 0x80000000u) ? (e & 0x7FFFFFFFu) : ~e;
    return __uint_as_float(u);
}
__device__ __forceinline__ float lrelu(float v, float s) {
    return (v > 0.f) ? v : s * v;
}
__device__ __forceinline__ unsigned f2tf32(float x) {
    unsigned r;
    asm("cvt.rna.tf32.f32 %0, %1;" : "=r"(r) : "f"(x));
    return r;
}
__device__ __forceinline__ void mma_tf32(float c[4],
                                         unsigned a0, unsigned a1, unsigned a2, unsigned a3,
                                         unsigned b0, unsigned b1) {
    asm volatile(
        "mma.sync.aligned.m16n8k8.row.col.f32.tf32.tf32.f32 "
        "{%0,%1,%2,%3}, {%4,%5,%6,%7}, {%8,%9}, {%0,%1,%2,%3};"
        : "+f"(c[0]), "+f"(c[1]), "+f"(c[2]), "+f"(c[3])
        : "r"(a0), "r"(a1), "r"(a2), "r"(a3), "r"(b0), "r"(b1));
}
__device__ __forceinline__ void red_add_v4(float* gptr, float a, float b, float c, float d) {
    asm volatile("red.global.add.v4.f32 [%0], {%1,%2,%3,%4};"
                 :: "l"(gptr), "f"(a), "f"(b), "f"(c), "f"(d) : "memory");
}

// ---------------- zero kernel (float4) ----------------
__global__ void zero4_kernel(float4* __restrict__ p, size_t n4) {
    size_t i = (size_t)blockIdx.x * blockDim.x + threadIdx.x;
    if (i < n4) p[i] = make_float4(0.f, 0.f, 0.f, 0.f);
}

// ---------------- TF32 tensor-core GEMM: C[M,Nn] = A[M,K] @ B[K,Nn] (+bias) ----
// 128x128 block tile, BK=16, 256 threads = 8 warps (2x4), warp tile 64x32.
// SPITCH=136: 136 mod 32 == 8, so frag-load banks = 8*tig + gID (+16*mi) —
// a perfect permutation of 0..31 -> conflict-free LDS for both A and B frags.
constexpr int TBM = 128, TBN = 128, TBK = 16;
constexpr int SPITCH = 136;

__global__ void __launch_bounds__(256, 2)
tgemm_kernel(const float* __restrict__ A, const float* __restrict__ B,
             float* __restrict__ C, int M, int Nn, int K,
             const float* __restrict__ bias) {
    __shared__ unsigned As[2][TBK][SPITCH];
    __shared__ unsigned Bs[2][TBK][SPITCH];

    const int tid  = threadIdx.x;
    const int lane = tid & 31;
    const int warp = tid >> 5;
    const int wr   = warp >> 2;      // 0..1
    const int wc   = warp & 3;       // 0..3
    const int gID  = lane >> 2;      // 0..7
    const int tig  = lane & 3;       // 0..3
    const int mBase = wr * 64;
    const int nBase = wc * 32;
    const int rowBase = blockIdx.y * TBM;
    const int colBase = blockIdx.x * TBN;

    // A staging: each thread loads 8 floats (2 float4) of one row
    const int ar = tid & 127;          // tile row
    const int ak = (tid >> 7) * 8;     // k offset: 0 or 8
    // B staging: each thread loads 8 floats, stride-16 within one k-row
    const int bk = tid >> 4;           // 0..15
    const int bc = tid & 15;           // col lane (stride 16)

    float acc[4][4][4];
#pragma unroll
    for (int mi = 0; mi < 4; mi++)
#pragma unroll
        for (int ni = 0; ni < 4; ni++)
#pragma unroll
            for (int q = 0; q < 4; q++) acc[mi][ni][q] = 0.f;

    float aReg[8], bReg[8];

    // ---- prologue: load tile 0 ----
    {
        const int gr = rowBase + ar;
        if (gr < M) {
            const float4 v0 = *reinterpret_cast<const float4*>(A + (size_t)gr * K + ak);
            const float4 v1 = *reinterpret_cast<const float4*>(A + (size_t)gr * K + ak + 4);
            aReg[0]=v0.x; aReg[1]=v0.y; aReg[2]=v0.z; aReg[3]=v0.w;
            aReg[4]=v1.x; aReg[5]=v1.y; aReg[6]=v1.z; aReg[7]=v1.w;
        } else {
#pragma unroll
            for (int j = 0; j < 8; j++) aReg[j] = 0.f;
        }
        const float* Bp = B + (size_t)bk * Nn;
#pragma unroll
        for (int j = 0; j < 8; j++) {
            int gc = colBase + bc + 16 * j;
            bReg[j] = (gc < Nn) ? Bp[gc] : 0.f;
        }
#pragma unroll
        for (int j = 0; j < 8; j++) As[0][ak + j][ar] = f2tf32(aReg[j]);
#pragma unroll
        for (int j = 0; j < 8; j++) Bs[0][bk][bc + 16 * j] = f2tf32(bReg[j]);
    }

    const int ntiles = K / TBK;
    for (int t = 0; t < ntiles; t++) {
        __syncthreads();
        const int buf = t & 1;

        // prefetch next tile into registers
        if (t + 1 < ntiles) {
            const int k0 = (t + 1) * TBK;
            const int gr = rowBase + ar;
            if (gr < M) {
                const float4 v0 = *reinterpret_cast<const float4*>(A + (size_t)gr * K + k0 + ak);
                const float4 v1 = *reinterpret_cast<const float4*>(A + (size_t)gr * K + k0 + ak + 4);
                aReg[0]=v0.x; aReg[1]=v0.y; aReg[2]=v0.z; aReg[3]=v0.w;
                aReg[4]=v1.x; aReg[5]=v1.y; aReg[6]=v1.z; aReg[7]=v1.w;
            } else {
#pragma unroll
                for (int j = 0; j < 8; j++) aReg[j] = 0.f;
            }
            const float* Bp = B + (size_t)(k0 + bk) * Nn;
#pragma unroll
            for (int j = 0; j < 8; j++) {
                int gc = colBase + bc + 16 * j;
                bReg[j] = (gc < Nn) ? Bp[gc] : 0.f;
            }
        }

        // mma over current buffer: two k=8 steps
#pragma unroll
        for (int ks = 0; ks < 2; ks++) {
            const int kk = ks * 8;
            unsigned af[4][4], bf[4][2];
#pragma unroll
            for (int mi = 0; mi < 4; mi++) {
                const int m0 = mBase + mi * 16 + gID;
                af[mi][0] = As[buf][kk + tig    ][m0];
                af[mi][1] = As[buf][kk + tig    ][m0 + 8];
                af[mi][2] = As[buf][kk + tig + 4][m0];
                af[mi][3] = As[buf][kk + tig + 4][m0 + 8];
            }
#pragma unroll
            for (int ni = 0; ni < 4; ni++) {
                const int n0 = nBase + ni * 8 + gID;
                bf[ni][0] = Bs[buf][kk + tig    ][n0];
                bf[ni][1] = Bs[buf][kk + tig + 4][n0];
            }
#pragma unroll
            for (int mi = 0; mi < 4; mi++)
#pragma unroll
                for (int ni = 0; ni < 4; ni++)
                    mma_tf32(acc[mi][ni], af[mi][0], af[mi][1], af[mi][2], af[mi][3],
                             bf[ni][0], bf[ni][1]);
        }

        // stage next tile into the other buffer
        if (t + 1 < ntiles) {
            const int nb = buf ^ 1;
#pragma unroll
            for (int j = 0; j < 8; j++) As[nb][ak + j][ar] = f2tf32(aReg[j]);
#pragma unroll
            for (int j = 0; j < 8; j++) Bs[nb][bk][bc + 16 * j] = f2tf32(bReg[j]);
        }
    }

    // ---- epilogue ----
#pragma unroll
    for (int mi = 0; mi < 4; mi++) {
        const int r0 = rowBase + mBase + mi * 16 + gID;
        const int r1 = r0 + 8;
#pragma unroll
        for (int ni = 0; ni < 4; ni++) {
            const int c0 = colBase + nBase + ni * 8 + tig * 2;
            const int c1 = c0 + 1;
            float b0v = 0.f, b1v = 0.f;
            if (bias) {
                if (c0 < Nn) b0v = bias[c0];
                if (c1 < Nn) b1v = bias[c1];
            }
            if (r0 < M) {
                if (c0 < Nn) C[(size_t)r0 * Nn + c0] = acc[mi][ni][0] + b0v;
                if (c1 < Nn) C[(size_t)r0 * Nn + c1] = acc[mi][ni][1] + b1v;
            }
            if (r1 < M) {
                if (c0 < Nn) C[(size_t)r1 * Nn + c0] = acc[mi][ni][2] + b0v;
                if (c1 < Nn) C[(size_t)r1 * Nn + c1] = acc[mi][ni][3] + b1v;
            }
        }
    }
}

// ---------------- attention projections: el/er [N,H] ----------------
// one warp per (node, head)
__global__ void attn_kernel(const float* __restrict__ feat,
                            const float* __restrict__ al,
                            const float* __restrict__ ar,
                            float* __restrict__ el, float* __restrict__ er) {
    int gw   = (blockIdx.x * blockDim.x + threadIdx.x) >> 5;
    int lane = threadIdx.x & 31;
    if (gw >= N_ * H_) return;
    int h = gw & (H_ - 1);

    float4 f = reinterpret_cast<const float4*>(feat + (size_t)gw * D_)[lane];
    float4 a = reinterpret_cast<const float4*>(al + h * D_)[lane];
    float4 r = reinterpret_cast<const float4*>(ar + h * D_)[lane];
    float sl = f.x*a.x + f.y*a.y + f.z*a.z + f.w*a.w;
    float sr = f.x*r.x + f.y*r.y + f.z*r.z + f.w*r.w;
#pragma unroll
    for (int o = 16; o > 0; o >>= 1) {
        sl += __shfl_down_sync(0xFFFFFFFFu, sl, o);
        sr += __shfl_down_sync(0xFFFFFFFFu, sr, o);
    }
    if (lane == 0) { el[gw] = sl; er[gw] = sr; }
}

// ---------------- edge pass 1: logits + segment max ----------------
__global__ void edge_logits_kernel(const int* __restrict__ src, const int* __restrict__ dst,
                                   const float* __restrict__ el, const float* __restrict__ er,
                                   float* __restrict__ ew, unsigned* __restrict__ m) {
    int i = blockIdx.x * blockDim.x + threadIdx.x;
    if (i >= E_ * H_) return;
    int e = i >> 2, h = i & 3;
    int s = src[e], d = dst[e];
    float v = el[s * H_ + h] + er[d * H_ + h];
    v = lrelu(v, 0.2f);
    ew[i] = v;
    atomicMax(&m[d * H_ + h], float_enc(v));
}

// ---------------- edge pass 2: exp + segment sum ----------------
__global__ void edge_exp_kernel(const int* __restrict__ dst,
                                float* __restrict__ ew, const unsigned* __restrict__ m,
                                float* __restrict__ ssum) {
    int i = blockIdx.x * blockDim.x + threadIdx.x;
    if (i >= E_ * H_) return;
    int e = i >> 2, h = i & 3;
    int d = dst[e];
    float w = expf(ew[i] - float_dec(m[d * H_ + h]));
    ew[i] = w;
    atomicAdd(&ssum[d * H_ + h], w);
}

// ---------------- edge pass 3: weighted scatter-add of messages ----------------
// one warp per (edge, head); each lane handles 4 consecutive dims; v4 reduction
__global__ void edge_scatter_kernel(const int* __restrict__ src, const int* __restrict__ dst,
                                    const float* __restrict__ ew, const float* __restrict__ ssum,
                                    const float* __restrict__ feat, float* __restrict__ acc) {
    int gw   = (blockIdx.x * blockDim.x + threadIdx.x) >> 5;
    int lane = threadIdx.x & 31;
    if (gw >= E_ * H_) return;
    int e = gw >> 2, h = gw & 3;
    int s = src[e], d = dst[e];
    float a = ew[gw] / ssum[d * H_ + h];

    float4 v = reinterpret_cast<const float4*>(feat + ((size_t)s * H_ + h) * D_)[lane];
    float* o = acc + ((size_t)d * H_ + h) * D_ + lane * 4;
    red_add_v4(o, v.x * a, v.y * a, v.z * a, v.w * a);
}

// ---------------- finalize: hout = act(acc0+b0) + act(acc1+b1) ----------------
__global__ void finalize_kernel(const float4* __restrict__ acc0, const float4* __restrict__ acc1,
                                const float4* __restrict__ b0, const float4* __restrict__ b1,
                                float4* __restrict__ hout, int activate) {
    size_t i = (size_t)blockIdx.x * blockDim.x + threadIdx.x;
    if (i >= NF_ / 4) return;
    int c4 = (int)(i & (F_ / 4 - 1));   // F_/4 = 128 column-vectors per row
    float4 v0 = acc0[i];
    float4 v1 = acc1[i];
    float4 x0 = b0[c4];
    float4 x1 = b1[c4];
    v0.x += x0.x; v0.y += x0.y; v0.z += x0.z; v0.w += x0.w;
    v1.x += x1.x; v1.y += x1.y; v1.z += x1.z; v1.w += x1.w;
    if (activate) {
        v0.x = lrelu(v0.x, 0.01f); v0.y = lrelu(v0.y, 0.01f);
        v0.z = lrelu(v0.z, 0.01f); v0.w = lrelu(v0.w, 0.01f);
        v1.x = lrelu(v1.x, 0.01f); v1.y = lrelu(v1.y, 0.01f);
        v1.z = lrelu(v1.z, 0.01f); v1.w = lrelu(v1.w, 0.01f);
    }
    float4 v;
    v.x = v0.x + v1.x; v.y = v0.y + v1.y; v.z = v0.z + v1.z; v.w = v0.w + v1.w;
    hout[i] = v;
}

// ---------------- host orchestration ----------------
extern "C" void kernel_launch(void* const* d_in, const int* in_sizes, int n_in,
                              void* d_out, int out_size) {
    const float* x       = (const float*)d_in[0];
    const int*   srcs[2] = {(const int*)d_in[1], (const int*)d_in[3]};
    const int*   dsts[2] = {(const int*)d_in[2], (const int*)d_in[4]};
    const float* W[3]    = {(const float*)d_in[5],  (const float*)d_in[9],  (const float*)d_in[13]};
    const float* AL[3]   = {(const float*)d_in[6],  (const float*)d_in[10], (const float*)d_in[14]};
    const float* AR[3]   = {(const float*)d_in[7],  (const float*)d_in[11], (const float*)d_in[15]};
    const float* BB[3]   = {(const float*)d_in[8],  (const float*)d_in[12], (const float*)d_in[16]};
    const float* Wout    = (const float*)d_in[17];
    const float* bout    = (const float*)d_in[18];
    float*       out     = (float*)d_out;

    void* p;
    cudaGetSymbolAddress(&p, g_feat); float*    feat = (float*)p;
    cudaGetSymbolAddress(&p, g_h0);   float*    h0   = (float*)p;
    cudaGetSymbolAddress(&p, g_h1);   float*    h1   = (float*)p;
    cudaGetSymbolAddress(&p, g_acc);  float*    acc  = (float*)p;
    cudaGetSymbolAddress(&p, g_el);   float*    el   = (float*)p;
    cudaGetSymbolAddress(&p, g_er);   float*    er   = (float*)p;
    cudaGetSymbolAddress(&p, g_m);    unsigned* mx   = (unsigned*)p;
    cudaGetSymbolAddress(&p, g_s);    float*    ss   = (float*)p;
    cudaGetSymbolAddress(&p, g_w);    float*    ew   = (float*)p;
    float* hb[2] = {h0, h1};

    const float* hin = x;
    int K = IN0_;

    for (int L = 0; L < 3; L++) {
        // reset per-type accumulators / segment stats
        {
            size_t n4 = (2 * NF_) / 4;
            zero4_kernel<<<(unsigned)((n4 + 255) / 256), 256>>>((float4*)acc, n4);
            size_t m4 = (2 * NH_) / 4;
            zero4_kernel<<<(unsigned)((m4 + 255) / 256), 256>>>((float4*)mx, m4);
            zero4_kernel<<<(unsigned)((m4 + 255) / 256), 256>>>((float4*)ss, m4);
        }
        for (int t = 0; t < 2; t++) {
            float*    featT = feat + (size_t)t * NF_;
            float*    accT  = acc  + (size_t)t * NF_;
            float*    elT   = el + (size_t)t * NH_;
            float*    erT   = er + (size_t)t * NH_;
            unsigned* mT    = mx + (size_t)t * NH_;
            float*    sT    = ss + (size_t)t * NH_;
            float*    wT    = ew + (size_t)t * EH_;

            dim3 grid((F_ + TBN - 1) / TBN, (N_ + TBM - 1) / TBM);
            tgemm_kernel<<<grid, 256>>>(hin, W[L] + (size_t)t * K * F_, featT,
                                        N_, F_, K, nullptr);

            attn_kernel<<<(N_ * H_ * 32 + 255) / 256, 256>>>(
                featT, AL[L] + t * H_ * D_, AR[L] + t * H_ * D_, elT, erT);

            edge_logits_kernel<<<(E_ * H_ + 255) / 256, 256>>>(
                srcs[t], dsts[t], elT, erT, wT, mT);

            edge_exp_kernel<<<(E_ * H_ + 255) / 256, 256>>>(dsts[t], wT, mT, sT);

            edge_scatter_kernel<<<(E_ * H_ + 7) / 8, 256>>>(
                srcs[t], dsts[t], wT, sT, featT, accT);
        }
        finalize_kernel<<<(unsigned)((NF_ / 4 + 255) / 256), 256>>>(
            (const float4*)acc, (const float4*)(acc + NF_),
            (const float4*)BB[L], (const float4*)(BB[L] + F_),
            (float4*)hb[L & 1], (L < 2) ? 1 : 0);
        hin = hb[L & 1];
        K = F_;
    }

    // output projection: [N, 512] @ [512, 2983] + bout
    dim3 grid((OUT_ + TBN - 1) / TBN, (N_ + TBM - 1) / TBM);
    tgemm_kernel<<<grid, 256>>>(hin, Wout, out, N_, OUT_, F_, bout);
}